// round 8
// baseline (speedup 1.0000x reference)
#include <cuda_runtime.h>
#include <cstdint>
#include <cstddef>

// Problem constants
#define S_IN   2048
#define NB     512
#define NSTEPS 2048
#define E_DIM  16
#define T_DIM  32
#define NCHUNK 16                    // 512 batches / 32 lanes

typedef unsigned long long u64;

// ---------------------------------------------------------------------------
// Packed f32x2 helpers (Blackwell)
// ---------------------------------------------------------------------------
__device__ __forceinline__ u64 pk2(float x) {
    u64 r; asm("mov.b64 %0, {%1, %1};" : "=l"(r) : "f"(x)); return r;
}
__device__ __forceinline__ u64 pkpair(float lo, float hi) {
    u64 r; asm("mov.b64 %0, {%1, %2};" : "=l"(r) : "f"(lo), "f"(hi)); return r;
}
__device__ __forceinline__ void upk(u64 v, float& lo, float& hi) {
    asm("mov.b64 {%0, %1}, %2;" : "=f"(lo), "=f"(hi) : "l"(v));
}
__device__ __forceinline__ void fma2(u64& d, u64 a, u64 b) {
    asm("fma.rn.f32x2 %0, %1, %2, %3;" : "=l"(d) : "l"(a), "l"(b), "l"(d));
}

// ---------------------------------------------------------------------------
// Device scratch
// d_pool[idx][b][e]: idx < S_IN -> relu'd input embedding emb[x[b][idx]];
//                    idx >= S_IN -> hidden state h (stored post-relu).
// ---------------------------------------------------------------------------
__device__ float d_pool[(size_t)(S_IN + NSTEPS) * NB * E_DIM];  // 128 MB
__device__ int   d_ri[NSTEPS];
__device__ int   d_c0[NSTEPS];
__device__ int   d_c1[NSTEPS];
__device__ int   d_inv[S_IN];                             // inv[out_idx[t]] = t
__device__ int   d_flag[NSTEPS * NCHUNK];                 // per (node, chunk) ready
__device__ int   d_is64;

// ---------------------------------------------------------------------------
// Prep: index-width detection, index conversion, inverse perm, flag clear.
// (Node order 0..NSTEPS-1 is already topological.)
// ---------------------------------------------------------------------------
__global__ __launch_bounds__(1024) void prep_kernel(
    const void* __restrict__ xp,
    const void* __restrict__ rip,
    const void* __restrict__ cip,
    const void* __restrict__ oip)
{
    __shared__ int s_flag;
    int tid = threadIdx.x;
    if (tid == 0) s_flag = 0;
    __syncthreads();

    // Detect int64 vs int32 x: int64 values < 2^31 -> every odd word is 0.
    {
        const int* xi = (const int*)xp;
        if (xi[2 * tid + 1] != 0) atomicOr(&s_flag, 1);
    }
    __syncthreads();
    int is64 = (s_flag == 0);
    if (tid == 0) d_is64 = is64;

    for (int t = tid; t < NSTEPS; t += 1024) {
        int ri, c0, c1, oi;
        if (is64) {
            ri = (int)((const long long*)rip)[t];
            c0 = (int)((const long long*)cip)[2 * t];
            c1 = (int)((const long long*)cip)[2 * t + 1];
            oi = (int)((const long long*)oip)[t];
        } else {
            ri = ((const int*)rip)[t];
            c0 = ((const int*)cip)[2 * t];
            c1 = ((const int*)cip)[2 * t + 1];
            oi = ((const int*)oip)[t];
        }
        d_ri[t] = ri; d_c0[t] = c0; d_c1[t] = c1;
        d_inv[oi] = t;
    }

    // Clear ready flags (graph replays reuse device state)
    for (int i = tid; i < NSTEPS * NCHUNK; i += 1024) d_flag[i] = 0;
}

// ---------------------------------------------------------------------------
// Embed: pool[s][b][:] = relu(emb[x[b][s]]). Transposed access via smem tile;
// per warp-row the pool store is 32 lanes x 64B = 2 KB contiguous. emb table
// (128 KB) stays L1/L2 resident.
// ---------------------------------------------------------------------------
__global__ __launch_bounds__(256) void embed_kernel(
    const void* __restrict__ xp,
    const float* __restrict__ emb)
{
    __shared__ int tile[32][33];
    const int is64 = d_is64;
    const int s0 = blockIdx.x * 32;
    const int b0 = blockIdx.y * 32;
    const int tx = threadIdx.x & 31;
    const int ty = threadIdx.x >> 5;

#pragma unroll
    for (int i = ty; i < 32; i += 8) {
        int v;
        if (is64) v = (int)((const long long*)xp)[(size_t)(b0 + i) * S_IN + s0 + tx];
        else      v = ((const int*)xp)[(size_t)(b0 + i) * S_IN + s0 + tx];
        tile[tx][i] = v;               // tile[s_local][b_local]
    }
    __syncthreads();

#pragma unroll
    for (int i = ty; i < 32; i += 8) {
        const int xv = tile[i][tx];
        const float4* p = (const float4*)(emb + (size_t)xv * E_DIM);
        float4* dst = (float4*)(d_pool + ((size_t)(s0 + i) * NB + (b0 + tx)) * E_DIM);
#pragma unroll
        for (int q = 0; q < 4; q++) {
            float4 v = __ldg(&p[q]);
            v.x = fmaxf(v.x, 0.0f); v.y = fmaxf(v.y, 0.0f);
            v.z = fmaxf(v.z, 0.0f); v.w = fmaxf(v.w, 0.0f);
            dst[q] = v;
        }
    }
}

// ---------------------------------------------------------------------------
// Dataflow wait: all lanes poll the (warp-uniform) flag, acquire via fence.
// ---------------------------------------------------------------------------
__device__ __forceinline__ void waitFlag(int i)
{
    volatile int* f = &d_flag[i];
    if (!*f) {
        while (!*f) __nanosleep(64);
    }
    __threadfence();
}

// Load one pool row (already relu'd): 4 independent LDG.128
__device__ __forceinline__ void loadVec(int idx, int b, float* v)
{
    const float4* p = (const float4*)(d_pool + ((size_t)idx * NB + b) * E_DIM);
#pragma unroll
    for (int i = 0; i < 4; i++) {
        float4 q = __ldg(&p[i]);
        v[4 * i + 0] = q.x; v[4 * i + 1] = q.y;
        v[4 * i + 2] = q.z; v[4 * i + 3] = q.w;
    }
}

// ---------------------------------------------------------------------------
// Scan: persistent dataflow kernel. Warp-task ti = node*16 + chunk covers
// 32 batches (b = chunk*32 + lane). Each task spin-waits only on its hidden
// children's ready flags; static in-order task assignment + full residency
// guarantees forward progress.
// ---------------------------------------------------------------------------
__global__ __launch_bounds__(256, 2) void scan_kernel(
    const float* __restrict__ attn_w,
    const float* __restrict__ attn_b,
    const float* __restrict__ out_w,
    const float* __restrict__ out_b)
{
    __shared__ u64 sWa2[E_DIM * 8];        // attn_w pairs [k][jj]
    __shared__ u64 sWo2[3 * E_DIM * 8];    // out_w  pairs [k][jj]
    __shared__ u64 sAb2[8], sOb2[8];

    for (int i = threadIdx.x; i < E_DIM * 8; i += blockDim.x) {
        float2 w = ((const float2*)attn_w)[i];
        sWa2[i] = pkpair(w.x, w.y);
    }
    for (int i = threadIdx.x; i < 3 * E_DIM * 8; i += blockDim.x) {
        float2 w = ((const float2*)out_w)[i];
        sWo2[i] = pkpair(w.x, w.y);
    }
    if (threadIdx.x < 8) {
        float2 wa = ((const float2*)attn_b)[threadIdx.x];
        float2 wo = ((const float2*)out_b)[threadIdx.x];
        sAb2[threadIdx.x] = pkpair(wa.x, wa.y);
        sOb2[threadIdx.x] = pkpair(wo.x, wo.y);
    }
    __syncthreads();

    const int lane  = threadIdx.x & 31;
    const int gwarp = (blockIdx.x * blockDim.x + threadIdx.x) >> 5;
    const int nW    = (gridDim.x * blockDim.x) >> 5;
    const int nTask = NSTEPS * NCHUNK;

    for (int ti = gwarp; ti < nTask; ti += nW) {
        const int node  = ti >> 4;
        const int chunk = ti & (NCHUNK - 1);
        const int b     = (chunk << 5) + lane;

        const int ri = __ldg(&d_ri[node]);
        const int c0 = __ldg(&d_c0[node]);
        const int c1 = __ldg(&d_c1[node]);

        // Wait for hidden children of this batch-chunk (warp-uniform)
        if (c0 >= S_IN) waitFlag((c0 - S_IN) * NCHUNK + chunk);
        if (c1 >= S_IN) waitFlag((c1 - S_IN) * NCHUNK + chunk);
        if (ri >= S_IN) waitFlag((ri - S_IN) * NCHUNK + chunk);  // defensive

        float r[E_DIM], v0[E_DIM], v1[E_DIM];
        loadVec(ri, b, r);
        loadVec(c0, b, v0);
        loadVec(c1, b, v1);

        // attn = r @ attn_w + attn_b
        u64 a2[8];
#pragma unroll
        for (int jj = 0; jj < 8; jj++) a2[jj] = sAb2[jj];
#pragma unroll
        for (int k = 0; k < E_DIM; k++) {
            const u64 rk = pk2(r[k]);
#pragma unroll
            for (int jj = 0; jj < 8; jj++)
                fma2(a2[jj], rk, sWa2[k * 8 + jj]);
        }
        float a[E_DIM];
#pragma unroll
        for (int jj = 0; jj < 8; jj++) upk(a2[jj], a[2 * jj], a[2 * jj + 1]);

        // applied children: ap = relu(attn * child)
#pragma unroll
        for (int j = 0; j < E_DIM; j++) {
            v0[j] = fmaxf(a[j] * v0[j], 0.0f);
            v1[j] = fmaxf(a[j] * v1[j], 0.0f);
        }

        // h = relu([r | ap0 | ap1] @ out_w + out_b)
        u64 h2[8];
#pragma unroll
        for (int jj = 0; jj < 8; jj++) h2[jj] = sOb2[jj];
#pragma unroll
        for (int k = 0; k < E_DIM; k++) {
            const u64 rk = pk2(r[k]);
            const u64 p0 = pk2(v0[k]);
            const u64 p1 = pk2(v1[k]);
#pragma unroll
            for (int jj = 0; jj < 8; jj++) {
                fma2(h2[jj], rk, sWo2[k * 8 + jj]);
                fma2(h2[jj], p0, sWo2[(E_DIM + k) * 8 + jj]);
                fma2(h2[jj], p1, sWo2[(2 * E_DIM + k) * 8 + jj]);
            }
        }
        float h[E_DIM];
#pragma unroll
        for (int jj = 0; jj < 8; jj++) upk(h2[jj], h[2 * jj], h[2 * jj + 1]);
#pragma unroll
        for (int j = 0; j < E_DIM; j++) h[j] = fmaxf(h[j], 0.0f);

        float4* hw = (float4*)(d_pool + ((size_t)(S_IN + node) * NB + b) * E_DIM);
#pragma unroll
        for (int i = 0; i < 4; i++)
            hw[i] = make_float4(h[4 * i], h[4 * i + 1], h[4 * i + 2], h[4 * i + 3]);

        // Publish: all lanes' stores -> fence -> flag
        __syncwarp();
        __threadfence();
        if (lane == 0) *(volatile int*)&d_flag[ti] = 1;
    }
}

// ---------------------------------------------------------------------------
// Emit: for each (s, b): node = inv[s]; z = h @ tag_w + tag_b; log-softmax;
// write y[b][tt][s] directly (lanes own consecutive s -> coalesced stores).
// ---------------------------------------------------------------------------
__global__ __launch_bounds__(256, 4) void emit_kernel(
    float* __restrict__ y,
    const float* __restrict__ tag_w,
    const float* __restrict__ tag_b)
{
    __shared__ u64 sWt2[E_DIM * 16];   // tag_w pairs [k][jj]
    __shared__ u64 sTb2[16];

    for (int i = threadIdx.x; i < E_DIM * 16; i += blockDim.x) {
        float2 w = ((const float2*)tag_w)[i];
        sWt2[i] = pkpair(w.x, w.y);
    }
    if (threadIdx.x < 16) {
        float2 w = ((const float2*)tag_b)[threadIdx.x];
        sTb2[threadIdx.x] = pkpair(w.x, w.y);
    }
    __syncthreads();

    const int s = blockIdx.x * 128 + (threadIdx.x & 127);
    const int b = blockIdx.y * 2 + (threadIdx.x >> 7);
    const int node = __ldg(&d_inv[s]);

    float h[E_DIM];
    {
        const float4* p = (const float4*)(d_pool + ((size_t)(S_IN + node) * NB + b) * E_DIM);
#pragma unroll
        for (int i = 0; i < 4; i++) {
            float4 q = __ldg(&p[i]);
            h[4 * i + 0] = q.x; h[4 * i + 1] = q.y;
            h[4 * i + 2] = q.z; h[4 * i + 3] = q.w;
        }
    }

    u64 z2[16];
#pragma unroll
    for (int jj = 0; jj < 16; jj++) z2[jj] = sTb2[jj];
#pragma unroll
    for (int k = 0; k < E_DIM; k++) {
        const u64 hk = pk2(h[k]);
#pragma unroll
        for (int jj = 0; jj < 16; jj++)
            fma2(z2[jj], hk, sWt2[k * 16 + jj]);
    }
    float z[T_DIM];
#pragma unroll
    for (int jj = 0; jj < 16; jj++) upk(z2[jj], z[2 * jj], z[2 * jj + 1]);

    float m = z[0];
#pragma unroll
    for (int j = 1; j < T_DIM; j++) m = fmaxf(m, z[j]);
    float ssum = 0.0f;
#pragma unroll
    for (int j = 0; j < T_DIM; j++) ssum += __expf(z[j] - m);
    const float lse = m + __logf(ssum);

    float* yb = y + (size_t)b * T_DIM * S_IN + s;
#pragma unroll
    for (int tt = 0; tt < T_DIM; tt++)
        yb[(size_t)tt * S_IN] = z[tt] - lse;
}

// ---------------------------------------------------------------------------
// Launch
// ---------------------------------------------------------------------------
extern "C" void kernel_launch(void* const* d_in, const int* in_sizes, int n_in,
                              void* d_out, int out_size)
{
    (void)in_sizes; (void)n_in; (void)out_size;
    const void*  x       = d_in[0];
    const float* emb     = (const float*)d_in[1];
    const float* attn_w  = (const float*)d_in[2];
    const float* attn_b  = (const float*)d_in[3];
    const float* out_w   = (const float*)d_in[4];
    const float* out_b   = (const float*)d_in[5];
    const float* tag_w   = (const float*)d_in[6];
    const float* tag_b   = (const float*)d_in[7];
    const void*  r_idx   = d_in[8];
    const void*  child   = d_in[9];
    const void*  out_idx = d_in[10];

    prep_kernel<<<1, 1024>>>(x, r_idx, child, out_idx);

    embed_kernel<<<dim3(S_IN / 32, NB / 32), 256>>>(x, emb);

    int dev = 0, sm = 148;
    cudaGetDevice(&dev);
    cudaDeviceGetAttribute(&sm, cudaDevAttrMultiProcessorCount, dev);
    if (sm < 1) sm = 1;

    // __launch_bounds__(256, 2) guarantees all scan blocks co-resident,
    // required for dataflow forward progress.
    scan_kernel<<<2 * sm, 256>>>(attn_w, attn_b, out_w, out_b);

    emit_kernel<<<dim3(S_IN / 128, NB / 2), 256>>>((float*)d_out, tag_w, tag_b);
}

// round 9
// speedup vs baseline: 1.0474x; 1.0474x over previous
#include <cuda_runtime.h>
#include <cstdint>
#include <cstddef>

// Problem constants
#define S_IN   2048
#define NB     512
#define NSTEPS 2048
#define E_DIM  16
#define T_DIM  32
#define VOCAB  2000                  // emb has VOCAB+1 rows; row VOCAB is PAD
#define NCHUNK 16                    // 512 batches / 32 lanes

typedef unsigned long long u64;

// ---------------------------------------------------------------------------
// Packed f32x2 helpers (Blackwell)
// ---------------------------------------------------------------------------
__device__ __forceinline__ u64 pk2(float x) {
    u64 r; asm("mov.b64 %0, {%1, %1};" : "=l"(r) : "f"(x)); return r;
}
__device__ __forceinline__ u64 pkpair(float lo, float hi) {
    u64 r; asm("mov.b64 %0, {%1, %2};" : "=l"(r) : "f"(lo), "f"(hi)); return r;
}
__device__ __forceinline__ void upk(u64 v, float& lo, float& hi) {
    asm("mov.b64 {%0, %1}, %2;" : "=f"(lo), "=f"(hi) : "l"(v));
}
__device__ __forceinline__ void fma2(u64& d, u64 a, u64 b) {
    asm("fma.rn.f32x2 %0, %1, %2, %3;" : "=l"(d) : "l"(a), "l"(b), "l"(d));
}

// ---------------------------------------------------------------------------
// Device scratch
// ---------------------------------------------------------------------------
__device__ float d_hidden[(size_t)NSTEPS * NB * E_DIM];     // 64 MB h states
__device__ int   d_xT[(size_t)S_IN * NB];                   // 4 MB xT[s][b]
__device__ float d_attnV [(VOCAB + 1) * E_DIM];             // attn row per vocab id
__device__ float d_hpartV[(VOCAB + 1) * E_DIM];             // r-part of h per vocab id
__device__ float d_embRelu[(VOCAB + 1) * E_DIM];            // relu(emb[v])
__device__ int   d_ri[NSTEPS];
__device__ int   d_c0[NSTEPS];
__device__ int   d_c1[NSTEPS];
__device__ int   d_inv[S_IN];                               // inv[out_idx[t]] = t
__device__ int   d_flag[NSTEPS * NCHUNK];                   // per (node, chunk) ready
__device__ int   d_is64;

// ---------------------------------------------------------------------------
// Prep: index-width detection, index conversion, inverse perm, flag clear.
// (Node order 0..NSTEPS-1 is already topological.)
// ---------------------------------------------------------------------------
__global__ __launch_bounds__(1024) void prep_kernel(
    const void* __restrict__ xp,
    const void* __restrict__ rip,
    const void* __restrict__ cip,
    const void* __restrict__ oip)
{
    __shared__ int s_flag;
    int tid = threadIdx.x;
    if (tid == 0) s_flag = 0;
    __syncthreads();

    // Detect int64 vs int32 x: int64 values < 2^31 -> every odd word is 0.
    {
        const int* xi = (const int*)xp;
        if (xi[2 * tid + 1] != 0) atomicOr(&s_flag, 1);
    }
    __syncthreads();
    int is64 = (s_flag == 0);
    if (tid == 0) d_is64 = is64;

    for (int t = tid; t < NSTEPS; t += 1024) {
        int ri, c0, c1, oi;
        if (is64) {
            ri = (int)((const long long*)rip)[t];
            c0 = (int)((const long long*)cip)[2 * t];
            c1 = (int)((const long long*)cip)[2 * t + 1];
            oi = (int)((const long long*)oip)[t];
        } else {
            ri = ((const int*)rip)[t];
            c0 = ((const int*)cip)[2 * t];
            c1 = ((const int*)cip)[2 * t + 1];
            oi = ((const int*)oip)[t];
        }
        d_ri[t] = ri; d_c0[t] = c0; d_c1[t] = c1;
        d_inv[oi] = t;
    }

    // Clear ready flags (graph replays reuse device state)
    for (int i = tid; i < NSTEPS * NCHUNK; i += 1024) d_flag[i] = 0;
}

// ---------------------------------------------------------------------------
// x transpose: xT[s][b] = (int)x[b][s]
// ---------------------------------------------------------------------------
__global__ __launch_bounds__(256) void xpose_kernel(const void* __restrict__ xp)
{
    __shared__ int tile[32][33];
    const int is64 = d_is64;
    const int s0 = blockIdx.x * 32;
    const int b0 = blockIdx.y * 32;
    const int tx = threadIdx.x & 31;
    const int ty = threadIdx.x >> 5;

#pragma unroll
    for (int i = ty; i < 32; i += 8) {
        int v;
        if (is64) v = (int)((const long long*)xp)[(size_t)(b0 + i) * S_IN + s0 + tx];
        else      v = ((const int*)xp)[(size_t)(b0 + i) * S_IN + s0 + tx];
        tile[tx][i] = v;
    }
    __syncthreads();
#pragma unroll
    for (int i = ty; i < 32; i += 8) {
        d_xT[(size_t)(s0 + i) * NB + b0 + tx] = tile[i][tx];
    }
}

// ---------------------------------------------------------------------------
// Tables: per vocab id v,
//   embRelu[v] = relu(emb[v])                      (PAD row forced to 0)
//   attnV[v]   = embRelu[v] @ attn_w + attn_b
//   hpartV[v]  = embRelu[v] @ out_w[0:16] + out_b
// One thread per v. Tiny (2001 x ~550 FLOP).
// ---------------------------------------------------------------------------
__global__ __launch_bounds__(256) void tables_kernel(
    const float* __restrict__ emb,
    const float* __restrict__ attn_w,
    const float* __restrict__ attn_b,
    const float* __restrict__ out_w,
    const float* __restrict__ out_b)
{
    const int v = blockIdx.x * blockDim.x + threadIdx.x;
    if (v > VOCAB) return;

    float er[E_DIM];
#pragma unroll
    for (int k = 0; k < E_DIM; k++) {
        float e = (v == VOCAB) ? 0.0f : emb[(size_t)v * E_DIM + k];  // PAD row zeroed
        er[k] = fmaxf(e, 0.0f);
    }

    float av[E_DIM], hv[E_DIM];
#pragma unroll
    for (int j = 0; j < E_DIM; j++) { av[j] = attn_b[j]; hv[j] = out_b[j]; }
#pragma unroll
    for (int k = 0; k < E_DIM; k++) {
        const float ek = er[k];
#pragma unroll
        for (int j = 0; j < E_DIM; j++) {
            av[j] = fmaf(ek, attn_w[k * E_DIM + j], av[j]);
            hv[j] = fmaf(ek, out_w[k * E_DIM + j], hv[j]);
        }
    }
#pragma unroll
    for (int j = 0; j < E_DIM; j++) {
        d_embRelu[v * E_DIM + j] = er[j];
        d_attnV [v * E_DIM + j] = av[j];
        d_hpartV[v * E_DIM + j] = hv[j];
    }
}

// ---------------------------------------------------------------------------
// Dataflow wait: all lanes poll the (warp-uniform) flag, acquire via fence.
// ---------------------------------------------------------------------------
__device__ __forceinline__ void waitFlag(int i)
{
    volatile int* f = &d_flag[i];
    if (!*f) {
        while (!*f) __nanosleep(64);
    }
    __threadfence();
}

// ---------------------------------------------------------------------------
// Scan: persistent dataflow kernel, warp-task ti = node*16 + chunk, 32 batches
// per task (b = chunk*32 + lane). Root contributions come from the vocab
// tables (attnV / hpartV); children come from embRelu (input slot, no wait)
// or d_hidden (hidden slot, flag wait). Only 256 FMA2 per task remain.
// ---------------------------------------------------------------------------
__global__ __launch_bounds__(256, 3) void scan_kernel()
{
    // out_w rows 16..47 as f32x2 pairs (children part), filled from tables? No:
    // loaded directly from global const in launch via params — instead copy here.
    __shared__ u64 sWo1[E_DIM * 8];   // out_w rows 16..31, pairs [k][jj]
    __shared__ u64 sWo2[E_DIM * 8];   // out_w rows 32..47, pairs [k][jj]
    // filled by kernel params below
    extern __shared__ char dummy[];   // (unused)

    // weights passed via __constant__-like global pointers is awkward; instead
    // sWo1/sWo2 are loaded in kernel_launch via a small copy into d_* tables?
    // Simpler: out_w is an input pointer; see scan_kernel2 signature below.
    // (This placeholder body is never used.)
}

// Real scan kernel (with parameters).
__global__ __launch_bounds__(256, 3) void scan_main_kernel(
    const float* __restrict__ out_w)
{
    __shared__ u64 sWo1[E_DIM * 8];   // out_w rows 16..31 pairs [k][jj]
    __shared__ u64 sWo2[E_DIM * 8];   // out_w rows 32..47 pairs [k][jj]

    for (int i = threadIdx.x; i < E_DIM * 8; i += blockDim.x) {
        float2 w1 = ((const float2*)(out_w + E_DIM * E_DIM))[i];
        float2 w2 = ((const float2*)(out_w + 2 * E_DIM * E_DIM))[i];
        sWo1[i] = pkpair(w1.x, w1.y);
        sWo2[i] = pkpair(w2.x, w2.y);
    }
    __syncthreads();

    const int lane  = threadIdx.x & 31;
    const int gwarp = (blockIdx.x * blockDim.x + threadIdx.x) >> 5;
    const int nW    = (gridDim.x * blockDim.x) >> 5;
    const int nTask = NSTEPS * NCHUNK;

    for (int ti = gwarp; ti < nTask; ti += nW) {
        const int node  = ti >> 4;
        const int chunk = ti & (NCHUNK - 1);
        const int b     = (chunk << 5) + lane;

        const int ri = __ldg(&d_ri[node]);   // always < S_IN (root is input)
        const int c0 = __ldg(&d_c0[node]);
        const int c1 = __ldg(&d_c1[node]);

        // Waits first (warp-uniform, only for hidden children)
        if (c0 >= S_IN) waitFlag((c0 - S_IN) * NCHUNK + chunk);
        if (c1 >= S_IN) waitFlag((c1 - S_IN) * NCHUNK + chunk);

        // Root: table gathers (attn row + h partial)
        const int xvr = __ldg(&d_xT[(size_t)ri * NB + b]);
        float att[E_DIM];
        u64   h2[8];
        {
            const float4* pa = (const float4*)(d_attnV + (size_t)xvr * E_DIM);
            const float4* ph = (const float4*)(d_hpartV + (size_t)xvr * E_DIM);
#pragma unroll
            for (int i = 0; i < 4; i++) {
                float4 qa = __ldg(&pa[i]);
                att[4 * i + 0] = qa.x; att[4 * i + 1] = qa.y;
                att[4 * i + 2] = qa.z; att[4 * i + 3] = qa.w;
                float4 qh = __ldg(&ph[i]);
                h2[2 * i + 0] = pkpair(qh.x, qh.y);
                h2[2 * i + 1] = pkpair(qh.z, qh.w);
            }
        }

        // Children rows (relu'd): table for input slots, d_hidden for hidden
        float v0[E_DIM], v1[E_DIM];
        {
            const float4* p0;
            if (c0 < S_IN) {
                int xv = __ldg(&d_xT[(size_t)c0 * NB + b]);
                p0 = (const float4*)(d_embRelu + (size_t)xv * E_DIM);
            } else {
                p0 = (const float4*)(d_hidden + ((size_t)(c0 - S_IN) * NB + b) * E_DIM);
            }
            const float4* p1;
            if (c1 < S_IN) {
                int xv = __ldg(&d_xT[(size_t)c1 * NB + b]);
                p1 = (const float4*)(d_embRelu + (size_t)xv * E_DIM);
            } else {
                p1 = (const float4*)(d_hidden + ((size_t)(c1 - S_IN) * NB + b) * E_DIM);
            }
#pragma unroll
            for (int i = 0; i < 4; i++) {
                float4 q0 = p0[i];     // plain loads (hidden rows are mutable)
                v0[4 * i + 0] = q0.x; v0[4 * i + 1] = q0.y;
                v0[4 * i + 2] = q0.z; v0[4 * i + 3] = q0.w;
                float4 q1 = p1[i];
                v1[4 * i + 0] = q1.x; v1[4 * i + 1] = q1.y;
                v1[4 * i + 2] = q1.z; v1[4 * i + 3] = q1.w;
            }
        }

        // ap = relu(att * child); hidden rows stored post-relu so relu(child)
        // is already applied for both table and hidden sources.
#pragma unroll
        for (int j = 0; j < E_DIM; j++) {
            v0[j] = fmaxf(att[j] * v0[j], 0.0f);
            v1[j] = fmaxf(att[j] * v1[j], 0.0f);
        }

        // h = relu(hpart + ap0 @ Wo[16:32] + ap1 @ Wo[32:48])
#pragma unroll
        for (int k = 0; k < E_DIM; k++) {
            const u64 p0 = pk2(v0[k]);
            const u64 p1 = pk2(v1[k]);
#pragma unroll
            for (int jj = 0; jj < 8; jj++) {
                fma2(h2[jj], p0, sWo1[k * 8 + jj]);
                fma2(h2[jj], p1, sWo2[k * 8 + jj]);
            }
        }
        float h[E_DIM];
#pragma unroll
        for (int jj = 0; jj < 8; jj++) upk(h2[jj], h[2 * jj], h[2 * jj + 1]);
#pragma unroll
        for (int j = 0; j < E_DIM; j++) h[j] = fmaxf(h[j], 0.0f);

        float4* hw = (float4*)(d_hidden + ((size_t)node * NB + b) * E_DIM);
#pragma unroll
        for (int i = 0; i < 4; i++)
            hw[i] = make_float4(h[4 * i], h[4 * i + 1], h[4 * i + 2], h[4 * i + 3]);

        // Publish: stores -> fence -> flag (proven R5 protocol)
        __syncwarp();
        __threadfence();
        if (lane == 0) *(volatile int*)&d_flag[ti] = 1;
    }
}

// ---------------------------------------------------------------------------
// Emit: thread pair per (s, b); each thread computes 16 of the 32 logits,
// pair combines max/sum via shfl_xor(16). Lanes 0-15 / 16-31 of a warp hold
// the same 16 consecutive s for the two tt-halves -> 64B store segments.
// ---------------------------------------------------------------------------
__global__ __launch_bounds__(256, 5) void emit_kernel(
    float* __restrict__ y,
    const float* __restrict__ tag_w,
    const float* __restrict__ tag_b)
{
    __shared__ u64 sWt2[E_DIM * 16];   // tag_w pairs [k][jj], jj in [0,16)
    __shared__ u64 sTb2[16];

    for (int i = threadIdx.x; i < E_DIM * 16; i += blockDim.x) {
        float2 w = ((const float2*)tag_w)[i];
        sWt2[i] = pkpair(w.x, w.y);
    }
    if (threadIdx.x < 16) {
        float2 w = ((const float2*)tag_b)[threadIdx.x];
        sTb2[threadIdx.x] = pkpair(w.x, w.y);
    }
    __syncthreads();

    const int w      = threadIdx.x >> 5;          // warp 0..7
    const int lane   = threadIdx.x & 31;
    const int slocal = (w << 4) | (lane & 15);    // 0..127
    const int thalf  = (lane >> 4) & 1;           // 0: tt 0-15, 1: tt 16-31
    const int s      = blockIdx.x * 128 + slocal;
    const int b      = blockIdx.y;
    const int node   = __ldg(&d_inv[s]);

    float h[E_DIM];
    {
        const float4* p = (const float4*)(d_hidden + ((size_t)node * NB + b) * E_DIM);
#pragma unroll
        for (int i = 0; i < 4; i++) {
            float4 q = __ldg(&p[i]);
            h[4 * i + 0] = q.x; h[4 * i + 1] = q.y;
            h[4 * i + 2] = q.z; h[4 * i + 3] = q.w;
        }
    }

    const int jbase = thalf * 8;
    u64 z2[8];
#pragma unroll
    for (int jj = 0; jj < 8; jj++) z2[jj] = sTb2[jbase + jj];
#pragma unroll
    for (int k = 0; k < E_DIM; k++) {
        const u64 hk = pk2(h[k]);
#pragma unroll
        for (int jj = 0; jj < 8; jj++)
            fma2(z2[jj], hk, sWt2[k * 16 + jbase + jj]);
    }
    float z[16];
#pragma unroll
    for (int jj = 0; jj < 8; jj++) upk(z2[jj], z[2 * jj], z[2 * jj + 1]);

    // log-softmax over 32 logits held 16-per-thread across the pair
    float m = z[0];
#pragma unroll
    for (int j = 1; j < 16; j++) m = fmaxf(m, z[j]);
    m = fmaxf(m, __shfl_xor_sync(0xffffffffu, m, 16));
    float ssum = 0.0f;
#pragma unroll
    for (int j = 0; j < 16; j++) ssum += __expf(z[j] - m);
    ssum += __shfl_xor_sync(0xffffffffu, ssum, 16);
    const float lse = m + __logf(ssum);

    float* yb = y + (size_t)b * T_DIM * S_IN + (size_t)(thalf * 16) * S_IN + s;
#pragma unroll
    for (int t = 0; t < 16; t++)
        yb[(size_t)t * S_IN] = z[t] - lse;
}

// ---------------------------------------------------------------------------
// Launch
// ---------------------------------------------------------------------------
extern "C" void kernel_launch(void* const* d_in, const int* in_sizes, int n_in,
                              void* d_out, int out_size)
{
    (void)in_sizes; (void)n_in; (void)out_size;
    const void*  x       = d_in[0];
    const float* emb     = (const float*)d_in[1];
    const float* attn_w  = (const float*)d_in[2];
    const float* attn_b  = (const float*)d_in[3];
    const float* out_w   = (const float*)d_in[4];
    const float* out_b   = (const float*)d_in[5];
    const float* tag_w   = (const float*)d_in[6];
    const float* tag_b   = (const float*)d_in[7];
    const void*  r_idx   = d_in[8];
    const void*  child   = d_in[9];
    const void*  out_idx = d_in[10];

    prep_kernel<<<1, 1024>>>(x, r_idx, child, out_idx);

    xpose_kernel<<<dim3(S_IN / 32, NB / 32), 256>>>(x);

    tables_kernel<<<(VOCAB + 1 + 255) / 256, 256>>>(emb, attn_w, attn_b, out_w, out_b);

    int dev = 0, sm = 148;
    cudaGetDevice(&dev);
    cudaDeviceGetAttribute(&sm, cudaDevAttrMultiProcessorCount, dev);
    if (sm < 1) sm = 1;

    // __launch_bounds__(256, 3): all scan blocks co-resident (required for
    // dataflow forward progress) at 24 warps/SM.
    scan_main_kernel<<<3 * sm, 256>>>(out_w);

    emit_kernel<<<dim3(S_IN / 128, NB), 256>>>((float*)d_out, tag_w, tag_b);
}

// round 12
// speedup vs baseline: 1.2963x; 1.2377x over previous
#include <cuda_runtime.h>
#include <cstdint>
#include <cstddef>

// Problem constants
#define S_IN   2048
#define NB     512
#define NSTEPS 2048
#define E_DIM  16
#define T_DIM  32
#define VOCAB  2000                  // emb has VOCAB+1 rows; row VOCAB is PAD
#define NCHUNK 16                    // 512 batches / 32 lanes

typedef unsigned long long u64;

// ---------------------------------------------------------------------------
// Packed f32x2 helpers (Blackwell)
// ---------------------------------------------------------------------------
__device__ __forceinline__ u64 pk2(float x) {
    u64 r; asm("mov.b64 %0, {%1, %1};" : "=l"(r) : "f"(x)); return r;
}
__device__ __forceinline__ u64 pkpair(float lo, float hi) {
    u64 r; asm("mov.b64 %0, {%1, %2};" : "=l"(r) : "f"(lo), "f"(hi)); return r;
}
__device__ __forceinline__ void upk(u64 v, float& lo, float& hi) {
    asm("mov.b64 {%0, %1}, %2;" : "=f"(lo), "=f"(hi) : "l"(v));
}
__device__ __forceinline__ void fma2(u64& d, u64 a, u64 b) {
    asm("fma.rn.f32x2 %0, %1, %2, %3;" : "=l"(d) : "l"(a), "l"(b), "l"(d));
}

// ---------------------------------------------------------------------------
// Device scratch
// ---------------------------------------------------------------------------
__device__ __align__(128) float d_hidden[(size_t)NSTEPS * NB * E_DIM]; // 64 MB
__device__ int   d_xT[(size_t)S_IN * NB];                 // 4 MB xT[s][b]
__device__ __align__(128) float d_attnHP[(VOCAB + 1) * 32];  // [v]: att[16] | hpart[16]
__device__ __align__(128) float d_embRelu[(VOCAB + 1) * E_DIM];
__device__ int   d_ri[NSTEPS];
__device__ int   d_c0[NSTEPS];
__device__ int   d_c1[NSTEPS];
__device__ int   d_inv[S_IN];                             // inv[out_idx[t]] = t
__device__ int   d_flag[NSTEPS * NCHUNK];                 // per (node, chunk) ready
__device__ int   d_is64;

// ---------------------------------------------------------------------------
// Prep: index-width detection, index conversion, inverse perm, flag clear.
// ---------------------------------------------------------------------------
__global__ __launch_bounds__(1024) void prep_kernel(
    const void* __restrict__ xp,
    const void* __restrict__ rip,
    const void* __restrict__ cip,
    const void* __restrict__ oip)
{
    __shared__ int s_flag;
    int tid = threadIdx.x;
    if (tid == 0) s_flag = 0;
    __syncthreads();

    {   // int64 x has zero odd words (values < 2^31)
        const int* xi = (const int*)xp;
        if (xi[2 * tid + 1] != 0) atomicOr(&s_flag, 1);
    }
    __syncthreads();
    int is64 = (s_flag == 0);
    if (tid == 0) d_is64 = is64;

    for (int t = tid; t < NSTEPS; t += 1024) {
        int ri, c0, c1, oi;
        if (is64) {
            ri = (int)((const long long*)rip)[t];
            c0 = (int)((const long long*)cip)[2 * t];
            c1 = (int)((const long long*)cip)[2 * t + 1];
            oi = (int)((const long long*)oip)[t];
        } else {
            ri = ((const int*)rip)[t];
            c0 = ((const int*)cip)[2 * t];
            c1 = ((const int*)cip)[2 * t + 1];
            oi = ((const int*)oip)[t];
        }
        d_ri[t] = ri; d_c0[t] = c0; d_c1[t] = c1;
        d_inv[oi] = t;
    }

    for (int i = tid; i < NSTEPS * NCHUNK; i += 1024) d_flag[i] = 0;
}

// ---------------------------------------------------------------------------
// x transpose: xT[s][b] = (int)x[b][s]
// ---------------------------------------------------------------------------
__global__ __launch_bounds__(256) void xpose_kernel(const void* __restrict__ xp)
{
    __shared__ int tile[32][33];
    const int is64 = d_is64;
    const int s0 = blockIdx.x * 32;
    const int b0 = blockIdx.y * 32;
    const int tx = threadIdx.x & 31;
    const int ty = threadIdx.x >> 5;

#pragma unroll
    for (int i = ty; i < 32; i += 8) {
        int v;
        if (is64) v = (int)((const long long*)xp)[(size_t)(b0 + i) * S_IN + s0 + tx];
        else      v = ((const int*)xp)[(size_t)(b0 + i) * S_IN + s0 + tx];
        tile[tx][i] = v;
    }
    __syncthreads();
#pragma unroll
    for (int i = ty; i < 32; i += 8) {
        d_xT[(size_t)(s0 + i) * NB + b0 + tx] = tile[i][tx];
    }
}

// ---------------------------------------------------------------------------
// Tables: per vocab id v:
//   embRelu[v]      = relu(emb[v])            (PAD row -> 0)
//   attnHP[v][0:16] = embRelu[v] @ attn_w + attn_b
//   attnHP[v][16:32]= embRelu[v] @ out_w[0:16] + out_b   (r-part of h)
// ---------------------------------------------------------------------------
__global__ __launch_bounds__(256) void tables_kernel(
    const float* __restrict__ emb,
    const float* __restrict__ attn_w,
    const float* __restrict__ attn_b,
    const float* __restrict__ out_w,
    const float* __restrict__ out_b)
{
    const int v = blockIdx.x * blockDim.x + threadIdx.x;
    if (v > VOCAB) return;

    float er[E_DIM];
#pragma unroll
    for (int k = 0; k < E_DIM; k++) {
        float e = (v == VOCAB) ? 0.0f : emb[(size_t)v * E_DIM + k];
        er[k] = fmaxf(e, 0.0f);
    }

    float av[E_DIM], hv[E_DIM];
#pragma unroll
    for (int j = 0; j < E_DIM; j++) { av[j] = attn_b[j]; hv[j] = out_b[j]; }
#pragma unroll
    for (int k = 0; k < E_DIM; k++) {
        const float ek = er[k];
#pragma unroll
        for (int j = 0; j < E_DIM; j++) {
            av[j] = fmaf(ek, attn_w[k * E_DIM + j], av[j]);
            hv[j] = fmaf(ek, out_w[k * E_DIM + j], hv[j]);
        }
    }
#pragma unroll
    for (int j = 0; j < E_DIM; j++) {
        d_embRelu[v * E_DIM + j]  = er[j];
        d_attnHP[v * 32 + j]      = av[j];
        d_attnHP[v * 32 + 16 + j] = hv[j];
    }
}

// ---------------------------------------------------------------------------
// Dataflow wait
// ---------------------------------------------------------------------------
__device__ __forceinline__ void waitFlag(int i)
{
    volatile int* f = &d_flag[i];
    if (!*f) {
        while (!*f) __nanosleep(64);
    }
    __threadfence();
}

// ---------------------------------------------------------------------------
// Scan: persistent dataflow kernel; warp-task ti = node*16 + chunk.
// All row traffic goes through per-warp smem staging so each LDG/STG touches
// few cache lines (cooperative gather/scatter).
// Stage rows are 36 floats (144 B, 16B-multiple): float4 accesses are aligned,
// and the per-lane read pattern stg[lane][4j] is conflict-free per LDS.128
// phase (banks (4*lane+4j) mod 32 distinct within each 8-lane phase).
// ---------------------------------------------------------------------------
#define STW 36
__global__ __launch_bounds__(256, 3) void scan_main_kernel(
    const float* __restrict__ out_w)
{
    __shared__ u64 sWo1[E_DIM * 8];   // out_w rows 16..31 pairs [k][jj]
    __shared__ u64 sWo2[E_DIM * 8];   // out_w rows 32..47 pairs [k][jj]
    __shared__ __align__(16) float stage[8][32][STW];

    for (int i = threadIdx.x; i < E_DIM * 8; i += blockDim.x) {
        float2 w1 = ((const float2*)(out_w + E_DIM * E_DIM))[i];
        float2 w2 = ((const float2*)(out_w + 2 * E_DIM * E_DIM))[i];
        sWo1[i] = pkpair(w1.x, w1.y);
        sWo2[i] = pkpair(w2.x, w2.y);
    }
    __syncthreads();

    const int lane = threadIdx.x & 31;
    const int wib  = threadIdx.x >> 5;
    float (*stg)[STW] = stage[wib];

    const int gwarp = (blockIdx.x * blockDim.x + threadIdx.x) >> 5;
    const int nW    = (gridDim.x * blockDim.x) >> 5;
    const int nTask = NSTEPS * NCHUNK;

    const int l4r = lane >> 2, l4q = lane & 3;   // 4 lanes / 64B row
    const int l8r = lane >> 3, l8q = lane & 7;   // 8 lanes / 128B row

    for (int ti = gwarp; ti < nTask; ti += nW) {
        const int node  = ti >> 4;
        const int chunk = ti & (NCHUNK - 1);
        const int b     = (chunk << 5) + lane;

        const int ri = __ldg(&d_ri[node]);   // always < S_IN
        const int c0 = __ldg(&d_c0[node]);
        const int c1 = __ldg(&d_c1[node]);

        // ---- root att+hpart: cooperative gather of 128B rows (flag-free) ----
        const int xvr = __ldg(&d_xT[(size_t)ri * NB + b]);
        float att[E_DIM];
        u64   h2[8];
        {
#pragma unroll
            for (int i = 0; i < 8; i++) {
                int r  = 4 * i + l8r;
                int xv = __shfl_sync(0xffffffffu, xvr, r);
                float4 q = __ldg((const float4*)(d_attnHP + (size_t)xv * 32) + l8q);
                *(float4*)&stg[r][l8q * 4] = q;
            }
            __syncwarp();
#pragma unroll
            for (int j = 0; j < 4; j++) {
                float4 qa = *(const float4*)&stg[lane][4 * j];
                att[4 * j + 0] = qa.x; att[4 * j + 1] = qa.y;
                att[4 * j + 2] = qa.z; att[4 * j + 3] = qa.w;
            }
#pragma unroll
            for (int j = 0; j < 4; j++) {
                float4 qh = *(const float4*)&stg[lane][16 + 4 * j];
                h2[2 * j + 0] = pkpair(qh.x, qh.y);
                h2[2 * j + 1] = pkpair(qh.z, qh.w);
            }
            __syncwarp();
        }

        // ---- children: input -> coop gather from embRelu (flag-free);
        //      hidden -> staged coalesced load of the contiguous 2KB block ----
        float v0[E_DIM], v1[E_DIM];
#pragma unroll
        for (int c = 0; c < 2; c++) {
            float* v = c ? v1 : v0;
            const int ci = c ? c1 : c0;
            if (ci < S_IN) {
                const int xvc = __ldg(&d_xT[(size_t)ci * NB + b]);
#pragma unroll
                for (int i = 0; i < 4; i++) {
                    int r  = 8 * i + l4r;
                    int xv = __shfl_sync(0xffffffffu, xvc, r);
                    float4 q = __ldg((const float4*)(d_embRelu + (size_t)xv * E_DIM) + l4q);
                    *(float4*)&stg[r][l4q * 4] = q;
                }
            } else {
                waitFlag((ci - S_IN) * NCHUNK + chunk);
                const float4* base = (const float4*)(d_hidden +
                    ((size_t)(ci - S_IN) * NB + (chunk << 5)) * E_DIM);
#pragma unroll
                for (int i = 0; i < 4; i++) {
                    float4 q = base[i * 32 + lane];     // coalesced 512B/instr
                    *(float4*)&stg[8 * i + l4r][l4q * 4] = q;
                }
            }
            __syncwarp();
#pragma unroll
            for (int j = 0; j < 4; j++) {
                float4 q = *(const float4*)&stg[lane][4 * j];
                v[4 * j + 0] = q.x; v[4 * j + 1] = q.y;
                v[4 * j + 2] = q.z; v[4 * j + 3] = q.w;
            }
            __syncwarp();
        }

        // ---- ap = relu(att * child) ----
#pragma unroll
        for (int j = 0; j < E_DIM; j++) {
            v0[j] = fmaxf(att[j] * v0[j], 0.0f);
            v1[j] = fmaxf(att[j] * v1[j], 0.0f);
        }

        // ---- h = relu(hpart + ap0 @ Wo[16:32] + ap1 @ Wo[32:48]) ----
#pragma unroll
        for (int k = 0; k < E_DIM; k++) {
            const u64 p0 = pk2(v0[k]);
            const u64 p1 = pk2(v1[k]);
#pragma unroll
            for (int jj = 0; jj < 8; jj++) {
                fma2(h2[jj], p0, sWo1[k * 8 + jj]);
                fma2(h2[jj], p1, sWo2[k * 8 + jj]);
            }
        }
        float h[E_DIM];
#pragma unroll
        for (int jj = 0; jj < 8; jj++) upk(h2[jj], h[2 * jj], h[2 * jj + 1]);
#pragma unroll
        for (int j = 0; j < E_DIM; j++) h[j] = fmaxf(h[j], 0.0f);

        // ---- h store: staged coalesced scatter ----
#pragma unroll
        for (int j = 0; j < 4; j++)
            *(float4*)&stg[lane][4 * j] =
                make_float4(h[4 * j], h[4 * j + 1], h[4 * j + 2], h[4 * j + 3]);
        __syncwarp();
        {
            float4* base = (float4*)(d_hidden +
                ((size_t)node * NB + (chunk << 5)) * E_DIM);
#pragma unroll
            for (int i = 0; i < 4; i++) {
                float4 q = *(const float4*)&stg[8 * i + l4r][l4q * 4];
                base[i * 32 + lane] = q;                // coalesced 512B/instr
            }
        }
        __syncwarp();

        // ---- publish ----
        __threadfence();
        if (lane == 0) *(volatile int*)&d_flag[ti] = 1;
    }
}

// ---------------------------------------------------------------------------
// Emit: thread pair per (s, b); 16 logits per thread; pair combine via
// shfl_xor(16). h rows fetched by cooperative gather (16 distinct rows/warp).
// estg rows are 20 floats (80 B, 16B-multiple) -> aligned float4 accesses;
// reads stg[lane&15][4j] are conflict-free per LDS.128 phase.
// ---------------------------------------------------------------------------
#define ETW 20
__global__ __launch_bounds__(256, 5) void emit_kernel(
    float* __restrict__ y,
    const float* __restrict__ tag_w,
    const float* __restrict__ tag_b)
{
    __shared__ u64 sWt2[E_DIM * 16];   // tag_w pairs [k][jj]
    __shared__ u64 sTb2[16];
    __shared__ __align__(16) float estg[8][16][ETW];

    for (int i = threadIdx.x; i < E_DIM * 16; i += blockDim.x) {
        float2 w = ((const float2*)tag_w)[i];
        sWt2[i] = pkpair(w.x, w.y);
    }
    if (threadIdx.x < 16) {
        float2 w = ((const float2*)tag_b)[threadIdx.x];
        sTb2[threadIdx.x] = pkpair(w.x, w.y);
    }
    __syncthreads();

    const int w      = threadIdx.x >> 5;
    const int lane   = threadIdx.x & 31;
    const int slocal = (w << 4) | (lane & 15);
    const int thalf  = (lane >> 4) & 1;
    const int s      = blockIdx.x * 128 + slocal;
    const int b      = blockIdx.y;
    const int node   = __ldg(&d_inv[s]);

    // Cooperative gather of the 16 distinct h rows (4 lanes x 16B per row)
    float (*stg)[ETW] = estg[w];
    {
        const int l4r = lane >> 2, l4q = lane & 3;
#pragma unroll
        for (int i = 0; i < 2; i++) {
            int r  = 8 * i + l4r;                        // 0..15
            int nd = __shfl_sync(0xffffffffu, node, r);  // lane r holds node for slocal r
            float4 q = __ldg((const float4*)(d_hidden +
                        ((size_t)nd * NB + b) * E_DIM) + l4q);
            *(float4*)&stg[r][l4q * 4] = q;
        }
        __syncwarp();
    }
    float h[E_DIM];
#pragma unroll
    for (int j = 0; j < 4; j++) {
        float4 q = *(const float4*)&stg[lane & 15][4 * j];
        h[4 * j + 0] = q.x; h[4 * j + 1] = q.y;
        h[4 * j + 2] = q.z; h[4 * j + 3] = q.w;
    }

    const int jbase = thalf * 8;
    u64 z2[8];
#pragma unroll
    for (int jj = 0; jj < 8; jj++) z2[jj] = sTb2[jbase + jj];
#pragma unroll
    for (int k = 0; k < E_DIM; k++) {
        const u64 hk = pk2(h[k]);
#pragma unroll
        for (int jj = 0; jj < 8; jj++)
            fma2(z2[jj], hk, sWt2[k * 16 + jbase + jj]);
    }
    float z[16];
#pragma unroll
    for (int jj = 0; jj < 8; jj++) upk(z2[jj], z[2 * jj], z[2 * jj + 1]);

    float m = z[0];
#pragma unroll
    for (int j = 1; j < 16; j++) m = fmaxf(m, z[j]);
    m = fmaxf(m, __shfl_xor_sync(0xffffffffu, m, 16));
    float ssum = 0.0f;
#pragma unroll
    for (int j = 0; j < 16; j++) ssum += __expf(z[j] - m);
    ssum += __shfl_xor_sync(0xffffffffu, ssum, 16);
    const float lse = m + __logf(ssum);

    float* yb = y + (size_t)b * T_DIM * S_IN + (size_t)(thalf * 16) * S_IN + s;
#pragma unroll
    for (int t = 0; t < 16; t++)
        yb[(size_t)t * S_IN] = z[t] - lse;
}

// ---------------------------------------------------------------------------
// Launch
// ---------------------------------------------------------------------------
extern "C" void kernel_launch(void* const* d_in, const int* in_sizes, int n_in,
                              void* d_out, int out_size)
{
    (void)in_sizes; (void)n_in; (void)out_size;
    const void*  x       = d_in[0];
    const float* emb     = (const float*)d_in[1];
    const float* attn_w  = (const float*)d_in[2];
    const float* attn_b  = (const float*)d_in[3];
    const float* out_w   = (const float*)d_in[4];
    const float* out_b   = (const float*)d_in[5];
    const float* tag_w   = (const float*)d_in[6];
    const float* tag_b   = (const float*)d_in[7];
    const void*  r_idx   = d_in[8];
    const void*  child   = d_in[9];
    const void*  out_idx = d_in[10];

    prep_kernel<<<1, 1024>>>(x, r_idx, child, out_idx);

    xpose_kernel<<<dim3(S_IN / 32, NB / 32), 256>>>(x);

    tables_kernel<<<(VOCAB + 1 + 255) / 256, 256>>>(emb, attn_w, attn_b, out_w, out_b);

    int dev = 0, sm = 148;
    cudaGetDevice(&dev);
    cudaDeviceGetAttribute(&sm, cudaDevAttrMultiProcessorCount, dev);
    if (sm < 1) sm = 1;

    // __launch_bounds__(256, 3): all scan blocks co-resident (dataflow
    // forward progress) at 24 warps/SM. 3 x ~39KB smem = ~117KB/SM < capacity.
    scan_main_kernel<<<3 * sm, 256>>>(out_w);

    emit_kernel<<<dim3(S_IN / 128, NB), 256>>>((float*)d_out, tag_w, tag_b);
}